// round 11
// baseline (speedup 1.0000x reference)
#include <cuda_runtime.h>
#include <cuda_bf16.h>
#include <cuda_fp16.h>
#include <cstdint>

// Problem constants
#define NN 50000      // nodes
#define NE 800000     // edges
#define HEADS 4
#define CH 64
#define F 256         // HEADS*CH == input dim for both layers

// GEMM tiling
#define BM 128
#define BN 128
#define BK 16

// ---------------- scratch (device globals; no allocation allowed) ----------------
__device__ float  g_h[NN * F];      // post-GEMM features (fp32)
__device__ __half g_h16[NN * F];    // fp16 copy for the gather path
__device__ float  g_feat[NN * F];   // layer-1 output / layer-2 input
__device__ float  g_asrc[NN * HEADS];
__device__ float  g_adst[NN * HEADS];
__device__ int    g_cnt[NN];        // in-degree histogram
__device__ int    g_start[NN + 1];  // CSR row starts (by dst)
__device__ int    g_cursor[NN];     // scatter cursors
__device__ int    g_csr_src[NE];    // src node id per CSR slot

// ---------------- helpers ----------------
__device__ __forceinline__ float lrelu(float x) { return x > 0.f ? x : 0.2f * x; }
__device__ __forceinline__ float elu1(float x)  { return x > 0.f ? x : expf(x) - 1.f; }

// fp16 mma: D += A(16x16, row) * B(16x8, col), fp32 accum
__device__ __forceinline__ void mma_f16(float* d, const uint32_t* a, const uint32_t* b) {
    asm volatile(
        "mma.sync.aligned.m16n8k16.row.col.f32.f16.f16.f32 "
        "{%0,%1,%2,%3}, {%4,%5,%6,%7}, {%8,%9}, {%0,%1,%2,%3};"
        : "+f"(d[0]), "+f"(d[1]), "+f"(d[2]), "+f"(d[3])
        : "r"(a[0]), "r"(a[1]), "r"(a[2]), "r"(a[3]), "r"(b[0]), "r"(b[1]));
}

// split fp32 into fp16 hi + fp16 lo(residual); pack as uint32 (hi in low half)
__device__ __forceinline__ uint32_t f16_split_pack(float f) {
    __half hi = __float2half_rn(f);
    __half lo = __float2half_rn(f - __half2float(hi));
    return (uint32_t)__half_as_ushort(hi) | ((uint32_t)__half_as_ushort(lo) << 16);
}

// swizzle for [k][*] smem: index ^ (((k>>1)&3)<<3)
__device__ __forceinline__ int swz(int k) { return ((k >> 1) & 3) << 3; }

// ---------------- GEMM: g_h = A[NN,256] @ B[256,256] via split-fp16 tensor cores ----
// 128x128 block tile, BK=16, 256 threads (8 warps, 4x2), warp tile 32x64.
// a = aH + aL (fp16 pair); D = aH*bH + aH*bL + aL*bH (aL*bL ~2^-22, dropped).
// SMEM: one uint32 per element = packed (hi,lo); PRMT assembles k-pair fragments.
__global__ void __launch_bounds__(256, 1)
gemm_f16s_kernel(const float* __restrict__ Ax, const float* __restrict__ B, int useFeat) {
    __shared__ uint32_t As[BK * BM];   // [k][m] packed (hi,lo)
    __shared__ uint32_t Bs[BK * BN];   // [k][n] packed (hi,lo)

    const float* A = useFeat ? g_feat : Ax;

    int tid  = threadIdx.x;
    int warp = tid >> 5;
    int lane = tid & 31;
    int wm = warp >> 1;              // 0..3
    int wn = warp & 1;               // 0..1
    int row0 = blockIdx.y * BM;
    int col0 = blockIdx.x * BN;
    int c = lane & 3;                // thread-in-group (k dimension quads)
    int r = lane >> 2;               // group id (0..7)

    float acc[2][8][4];
#pragma unroll
    for (int mt = 0; mt < 2; mt++)
#pragma unroll
        for (int nt = 0; nt < 8; nt++)
#pragma unroll
            for (int i = 0; i < 4; i++) acc[mt][nt][i] = 0.f;

    // ---- gmem load mapping ----
    int am = tid >> 1;               // A row within tile (0..127)
    int ak = (tid & 1) * 8;          // A k offset (0 or 8)
    int bk = tid >> 4;               // B k row (0..15)
    int bn = (tid & 15) * 8;         // B n offset (0..120, step 8)

    float4 pa0, pa1, pb0, pb1;
    {
        int grow = row0 + am;
        if (grow < NN) {
            pa0 = *(const float4*)&A[grow * F + ak];
            pa1 = *(const float4*)&A[grow * F + ak + 4];
        } else {
            pa0 = make_float4(0.f, 0.f, 0.f, 0.f);
            pa1 = pa0;
        }
        pb0 = *(const float4*)&B[bk * F + col0 + bn];
        pb1 = *(const float4*)&B[bk * F + col0 + bn + 4];
    }

    for (int k0 = 0; k0 < F; k0 += BK) {
        // ---- store current tile to smem as packed fp16 splits ----
        float av[8] = {pa0.x, pa0.y, pa0.z, pa0.w, pa1.x, pa1.y, pa1.z, pa1.w};
#pragma unroll
        for (int j = 0; j < 8; j++) {
            int kk = ak + j;
            As[kk * BM + (am ^ swz(kk))] = f16_split_pack(av[j]);
        }
        float bv[8] = {pb0.x, pb0.y, pb0.z, pb0.w, pb1.x, pb1.y, pb1.z, pb1.w};
        {
            uint32_t pb[8];
#pragma unroll
            for (int j = 0; j < 8; j++) pb[j] = f16_split_pack(bv[j]);
            int bbase = bk * BN + (bn ^ swz(bk));   // bn 8-aligned; xor bits 3..4
            *(uint4*)&Bs[bbase]     = make_uint4(pb[0], pb[1], pb[2], pb[3]);
            *(uint4*)&Bs[bbase + 4] = make_uint4(pb[4], pb[5], pb[6], pb[7]);
        }
        __syncthreads();

        // ---- prefetch next tile ----
        if (k0 + BK < F) {
            int kn = k0 + BK;
            int grow = row0 + am;
            if (grow < NN) {
                pa0 = *(const float4*)&A[grow * F + kn + ak];
                pa1 = *(const float4*)&A[grow * F + kn + ak + 4];
            } else {
                pa0 = make_float4(0.f, 0.f, 0.f, 0.f);
                pa1 = pa0;
            }
            pb0 = *(const float4*)&B[(kn + bk) * F + col0 + bn];
            pb1 = *(const float4*)&B[(kn + bk) * F + col0 + bn + 4];
        }

        // ---- compute: one m16n8k16 step covers the whole BK=16 tile ----
        // this thread's A/B k-columns: 2c, 2c+1, 2c+8, 2c+9; all share xor = c<<3
        uint32_t aH[2][4], aL[2][4];
#pragma unroll
        for (int mt = 0; mt < 2; mt++) {
            int m0 = wm * 32 + mt * 16;
            int xm  = (m0 + r)     ^ (c << 3);
            int xm8 = (m0 + r + 8) ^ (c << 3);
            uint32_t w_r_k0  = As[(2 * c)     * BM + xm];
            uint32_t w_r_k1  = As[(2 * c + 1) * BM + xm];
            uint32_t w_r8_k0 = As[(2 * c)     * BM + xm8];
            uint32_t w_r8_k1 = As[(2 * c + 1) * BM + xm8];
            uint32_t w_r_k8  = As[(2 * c + 8) * BM + xm];
            uint32_t w_r_k9  = As[(2 * c + 9) * BM + xm];
            uint32_t w_r8_k8 = As[(2 * c + 8) * BM + xm8];
            uint32_t w_r8_k9 = As[(2 * c + 9) * BM + xm8];
            aH[mt][0] = __byte_perm(w_r_k0,  w_r_k1,  0x5410);
            aL[mt][0] = __byte_perm(w_r_k0,  w_r_k1,  0x7632);
            aH[mt][1] = __byte_perm(w_r8_k0, w_r8_k1, 0x5410);
            aL[mt][1] = __byte_perm(w_r8_k0, w_r8_k1, 0x7632);
            aH[mt][2] = __byte_perm(w_r_k8,  w_r_k9,  0x5410);
            aL[mt][2] = __byte_perm(w_r_k8,  w_r_k9,  0x7632);
            aH[mt][3] = __byte_perm(w_r8_k8, w_r8_k9, 0x5410);
            aL[mt][3] = __byte_perm(w_r8_k8, w_r8_k9, 0x7632);
        }
#pragma unroll
        for (int nt = 0; nt < 8; nt++) {
            int n_ = wn * 64 + nt * 8 + r;
            int xn = n_ ^ (c << 3);
            uint32_t w0 = Bs[(2 * c)     * BN + xn];
            uint32_t w1 = Bs[(2 * c + 1) * BN + xn];
            uint32_t w2 = Bs[(2 * c + 8) * BN + xn];
            uint32_t w3 = Bs[(2 * c + 9) * BN + xn];
            uint32_t bH[2], bL[2];
            bH[0] = __byte_perm(w0, w1, 0x5410);
            bL[0] = __byte_perm(w0, w1, 0x7632);
            bH[1] = __byte_perm(w2, w3, 0x5410);
            bL[1] = __byte_perm(w2, w3, 0x7632);
#pragma unroll
            for (int mt = 0; mt < 2; mt++) {
                mma_f16(acc[mt][nt], aH[mt], bH);
                mma_f16(acc[mt][nt], aH[mt], bL);
                mma_f16(acc[mt][nt], aL[mt], bH);
            }
        }
        __syncthreads();
    }

    // epilogue -> g_h (fp32) + g_h16 (fp16 gather copy); D layout same as m16n8k8
#pragma unroll
    for (int mt = 0; mt < 2; mt++) {
        int rb = row0 + wm * 32 + mt * 16 + r;
#pragma unroll
        for (int nt = 0; nt < 8; nt++) {
            int cb = col0 + wn * 64 + nt * 8 + 2 * c;
            if (rb < NN) {
                *(float2*)&g_h[rb * F + cb] = make_float2(acc[mt][nt][0], acc[mt][nt][1]);
                *(__half2*)&g_h16[rb * F + cb] = __floats2half2_rn(acc[mt][nt][0], acc[mt][nt][1]);
            }
            if (rb + 8 < NN) {
                *(float2*)&g_h[(rb + 8) * F + cb] = make_float2(acc[mt][nt][2], acc[mt][nt][3]);
                *(__half2*)&g_h16[(rb + 8) * F + cb] = __floats2half2_rn(acc[mt][nt][2], acc[mt][nt][3]);
            }
        }
    }
}

// ---------------- attention coefficients: a_src, a_dst per (node, head) ----------------
__global__ void attn_kernel(const float* __restrict__ att_src,
                            const float* __restrict__ att_dst) {
    int idx = blockIdx.x * blockDim.x + threadIdx.x;
    if (idx >= NN * HEADS) return;
    int n = idx >> 2;
    int h = idx & 3;
    const float4* hp = (const float4*)&g_h[n * F + h * CH];
    const float4* as = (const float4*)&att_src[h * CH];
    const float4* ad = (const float4*)&att_dst[h * CH];
    float ssum = 0.f, dsum = 0.f;
#pragma unroll
    for (int i = 0; i < 16; i++) {
        float4 v = hp[i];
        float4 s4 = as[i];
        float4 d4 = ad[i];
        ssum += v.x * s4.x + v.y * s4.y + v.z * s4.z + v.w * s4.w;
        dsum += v.x * d4.x + v.y * d4.y + v.z * d4.z + v.w * d4.w;
    }
    g_asrc[idx] = ssum;
    g_adst[idx] = dsum;
}

// ---------------- CSR build ----------------
__global__ void hist_kernel(const int* __restrict__ dst) {
    int e = blockIdx.x * blockDim.x + threadIdx.x;
    if (e < NE) atomicAdd(&g_cnt[dst[e]], 1);
}

// single-block exclusive scan over g_cnt -> g_start, g_cursor (int4 per thread)
__global__ void scan_kernel() {
    __shared__ int warp_sums[32];
    __shared__ int s_carry;
    int tid = threadIdx.x;
    int lane = tid & 31;
    int wid = tid >> 5;
    if (tid == 0) s_carry = 0;
    __syncthreads();
    for (int base = 0; base < NN; base += 4096) {
        int i = base + tid * 4;
        int4 v = make_int4(0, 0, 0, 0);
        if (i < NN) v = *(const int4*)&g_cnt[i];     // NN % 4 == 0
        int t = v.x + v.y + v.z + v.w;
        int x = t;
#pragma unroll
        for (int o = 1; o < 32; o <<= 1) {
            int y = __shfl_up_sync(0xffffffffu, x, o);
            if (lane >= o) x += y;
        }
        if (lane == 31) warp_sums[wid] = x;
        __syncthreads();
        if (wid == 0) {
            int ws = warp_sums[lane];
#pragma unroll
            for (int o = 1; o < 32; o <<= 1) {
                int y = __shfl_up_sync(0xffffffffu, ws, o);
                if (lane >= o) ws += y;
            }
            warp_sums[lane] = ws;
        }
        __syncthreads();
        int excl = x - t + (wid > 0 ? warp_sums[wid - 1] : 0) + s_carry;
        if (i < NN) {
            int4 e4 = make_int4(excl, excl + v.x, excl + v.x + v.y, excl + v.x + v.y + v.z);
            *(int4*)&g_start[i]  = e4;
            *(int4*)&g_cursor[i] = e4;
        }
        __syncthreads();
        if (tid == 0) s_carry += warp_sums[31];
        __syncthreads();
    }
    if (tid == 0) g_start[NN] = s_carry;
}

__global__ void scatter_kernel(const int* __restrict__ src,
                               const int* __restrict__ dst) {
    int e = blockIdx.x * blockDim.x + threadIdx.x;
    if (e >= NE) return;
    int d = dst[e];
    int p = atomicAdd(&g_cursor[d], 1);
    g_csr_src[p] = src[e];
}

// ---------------- fused aggregation: warp per dst node, register accumulators ------
// out[d] = elu( (wself*h[d] + sum_e w_e*h16[src_e]) / (wself + sum w_e + 1e-16) + bias )
__global__ void __launch_bounds__(256)
agg_kernel(const float* __restrict__ bias, float* __restrict__ outp, int toFeat) {
    int d = blockIdx.x * 8 + (threadIdx.x >> 5);
    if (d >= NN) return;
    int lane = threadIdx.x & 31;
    int h = lane >> 3;                      // head for this lane's 8 columns

    float adst_h = g_adst[d * 4 + h];
    float wself  = expf(lrelu(g_asrc[d * 4 + h] + adst_h));

    const float4* hp = (const float4*)&g_h[d * F + lane * 8];
    float4 a0 = hp[0], a1 = hp[1];
    float4 acc0 = make_float4(wself * a0.x, wself * a0.y, wself * a0.z, wself * a0.w);
    float4 acc1 = make_float4(wself * a1.x, wself * a1.y, wself * a1.z, wself * a1.w);
    float denom = wself;

    int s0 = g_start[d];
    int s1 = g_start[d + 1];

    for (int base = s0; base < s1; base += 32) {
        int cnt = min(32, s1 - base);
        int sidx = (lane < cnt) ? g_csr_src[base + lane] : 0;
        int nsub = (cnt + 7) >> 3;
        for (int sub = 0; sub < nsub; sub++) {
            // 32 lanes compute weights for 8 edges x 4 heads in parallel
            int sw = __shfl_sync(0xffffffffu, sidx, sub * 8 + (lane & 7));
            float wl = expf(lrelu(g_asrc[sw * 4 + h] + adst_h));
            int jend = min(8, cnt - sub * 8);
#pragma unroll 4
            for (int j = 0; j < jend; j++) {
                int s  = __shfl_sync(0xffffffffu, sidx, sub * 8 + j);
                float w = __shfl_sync(0xffffffffu, wl, (lane & 24) + j);
                uint4 raw = *(const uint4*)&g_h16[s * F + lane * 8];
                float2 f0 = __half22float2(*(__half2*)&raw.x);
                float2 f1 = __half22float2(*(__half2*)&raw.y);
                float2 f2 = __half22float2(*(__half2*)&raw.z);
                float2 f3 = __half22float2(*(__half2*)&raw.w);
                acc0.x += w * f0.x; acc0.y += w * f0.y;
                acc0.z += w * f1.x; acc0.w += w * f1.y;
                acc1.x += w * f2.x; acc1.y += w * f2.y;
                acc1.z += w * f3.x; acc1.w += w * f3.y;
                denom += w;
            }
        }
    }

    float inv = 1.f / (denom + 1e-16f);
    float4 b0 = *(const float4*)&bias[lane * 8];
    float4 b1 = *(const float4*)&bias[lane * 8 + 4];
    acc0.x = elu1(acc0.x * inv + b0.x);
    acc0.y = elu1(acc0.y * inv + b0.y);
    acc0.z = elu1(acc0.z * inv + b0.z);
    acc0.w = elu1(acc0.w * inv + b0.w);
    acc1.x = elu1(acc1.x * inv + b1.x);
    acc1.y = elu1(acc1.y * inv + b1.y);
    acc1.z = elu1(acc1.z * inv + b1.z);
    acc1.w = elu1(acc1.w * inv + b1.w);

    float* dp = (toFeat ? g_feat : outp) + d * F + lane * 8;
    *(float4*)dp       = acc0;
    *(float4*)(dp + 4) = acc1;
}

// ---------------- launch ----------------
static void run_layer(const float* x_or_null, int useFeat,
                      const float* W, const float* att_src, const float* att_dst,
                      const float* bias, float* outp, int toFeat) {
    dim3 gemmGrid(F / BN, (NN + BM - 1) / BM);
    gemm_f16s_kernel<<<gemmGrid, 256>>>(x_or_null, W, useFeat);

    int nh = NN * HEADS;
    attn_kernel<<<(nh + 255) / 256, 256>>>(att_src, att_dst);
    agg_kernel<<<(NN + 7) / 8, 256>>>(bias, outp, toFeat);
}

extern "C" void kernel_launch(void* const* d_in, const int* in_sizes, int n_in,
                              void* d_out, int out_size) {
    const float* x        = (const float*)d_in[0];
    const int*   ei       = (const int*)  d_in[1];
    const float* W1       = (const float*)d_in[2];
    const float* att_src1 = (const float*)d_in[3];
    const float* att_dst1 = (const float*)d_in[4];
    const float* b1       = (const float*)d_in[5];
    const float* W2       = (const float*)d_in[6];
    const float* att_src2 = (const float*)d_in[7];
    const float* att_dst2 = (const float*)d_in[8];
    const float* b2       = (const float*)d_in[9];
    float* out = (float*)d_out;

    const int* src = ei;            // edge_index[0]
    const int* dst = ei + NE;       // edge_index[1]

    // CSR build (shared by both layers)
    void* cnt_ptr = nullptr;
    cudaGetSymbolAddress(&cnt_ptr, g_cnt);
    cudaMemsetAsync(cnt_ptr, 0, NN * sizeof(int));
    hist_kernel<<<(NE + 255) / 256, 256>>>(dst);
    scan_kernel<<<1, 1024>>>();
    scatter_kernel<<<(NE + 255) / 256, 256>>>(src, dst);

    // layer 1: x -> g_feat
    run_layer(x, 0, W1, att_src1, att_dst1, b1, nullptr, 1);
    // layer 2: g_feat -> out
    run_layer(nullptr, 1, W2, att_src2, att_dst2, b2, out, 0);
}

// round 12
// speedup vs baseline: 1.4220x; 1.4220x over previous
#include <cuda_runtime.h>
#include <cuda_bf16.h>
#include <cuda_fp16.h>
#include <cstdint>

// Problem constants
#define NN 50000      // nodes
#define NE 800000     // edges
#define HEADS 4
#define CH 64
#define F 256         // HEADS*CH == input dim for both layers

// GEMM tiling
#define BM 128
#define BN 128
#define BK 16

// ---------------- scratch (device globals; no allocation allowed) ----------------
__device__ float  g_h[NN * F];      // post-GEMM features (fp32)
__device__ __half g_h16[NN * F];    // fp16 copy for the gather path
__device__ float  g_feat[NN * F];   // layer-1 output / layer-2 input
__device__ float  g_asrc[NN * HEADS];
__device__ float  g_adst[NN * HEADS];
__device__ int    g_cnt[NN];        // in-degree histogram
__device__ int    g_start[NN + 1];  // CSR row starts (by dst)
__device__ int    g_cursor[NN];     // scatter cursors
__device__ int    g_csr_src[NE];    // src node id per CSR slot

// ---------------- helpers ----------------
__device__ __forceinline__ float lrelu(float x) { return x > 0.f ? x : 0.2f * x; }
__device__ __forceinline__ float elu1(float x)  { return x > 0.f ? x : expf(x) - 1.f; }

// tf32 mma: D += A(16x8, row) * B(8x8, col), fp32 accum
__device__ __forceinline__ void mma_tf32(float* d, const uint32_t* a, const uint32_t* b) {
    asm volatile(
        "mma.sync.aligned.m16n8k8.row.col.f32.tf32.tf32.f32 "
        "{%0,%1,%2,%3}, {%4,%5,%6,%7}, {%8,%9}, {%0,%1,%2,%3};"
        : "+f"(d[0]), "+f"(d[1]), "+f"(d[2]), "+f"(d[3])
        : "r"(a[0]), "r"(a[1]), "r"(a[2]), "r"(a[3]), "r"(b[0]), "r"(b[1]));
}

// split fp32 into tf32 hi + tf32 lo (truncation; lo*lo term ~2^-22, dropped)
__device__ __forceinline__ void tf32_split(float f, uint32_t& hi, uint32_t& lo) {
    hi = __float_as_uint(f) & 0xFFFFE000u;
    float lf = f - __uint_as_float(hi);
    lo = __float_as_uint(lf) & 0xFFFFE000u;
}

// ---------------- GEMM: g_h = A[NN,256] @ B[256,256] via 3xTF32 tensor cores --------
// 128x128 block tile, BK=16, 256 threads (8 warps, 4x2), warp tile 32x64.
// XOR-swizzled SMEM [k][m] / [k][n]; split-in-loop.
// __launch_bounds__(256, 2): cap regs at 128 -> 2 CTAs/SM (16 warps) for latency hiding.
__global__ void __launch_bounds__(256, 2)
gemm_tf32_kernel(const float* __restrict__ Ax, const float* __restrict__ B, int useFeat) {
    __shared__ float As[BK * BM];
    __shared__ float Bs[BK * BN];

    const float* A = useFeat ? g_feat : Ax;

    int tid  = threadIdx.x;
    int warp = tid >> 5;
    int lane = tid & 31;
    int wm = warp >> 1;              // 0..3
    int wn = warp & 1;               // 0..1
    int row0 = blockIdx.y * BM;
    int col0 = blockIdx.x * BN;
    int c = lane & 3;                // quad column
    int r = lane >> 2;               // quad row (0..7)

    float acc[2][8][4];
#pragma unroll
    for (int mt = 0; mt < 2; mt++)
#pragma unroll
        for (int nt = 0; nt < 8; nt++)
#pragma unroll
            for (int i = 0; i < 4; i++) acc[mt][nt][i] = 0.f;

    // ---- gmem load mapping ----
    int am = tid >> 1;               // A row within tile (0..127)
    int ak = (tid & 1) * 8;          // A k offset (0 or 8)
    int bk = tid >> 4;               // B k row (0..15)
    int bn = (tid & 15) * 8;         // B n offset (0..120, step 8)

    float4 pa0, pa1, pb0, pb1;
    {
        int grow = row0 + am;
        if (grow < NN) {
            pa0 = *(const float4*)&A[grow * F + ak];
            pa1 = *(const float4*)&A[grow * F + ak + 4];
        } else {
            pa0 = make_float4(0.f, 0.f, 0.f, 0.f);
            pa1 = pa0;
        }
        pb0 = *(const float4*)&B[bk * F + col0 + bn];
        pb1 = *(const float4*)&B[bk * F + col0 + bn + 4];
    }

    for (int k0 = 0; k0 < F; k0 += BK) {
        // store current tile to smem (A transposed + swizzled)
        float av[8] = {pa0.x, pa0.y, pa0.z, pa0.w, pa1.x, pa1.y, pa1.z, pa1.w};
#pragma unroll
        for (int j = 0; j < 8; j++) {
            int kk = ak + j;
            As[kk * BM + (am ^ ((kk & 3) << 3))] = av[j];
        }
        *(float4*)&Bs[bk * BN + (bn ^ ((bk & 3) << 3))]       = pb0;
        *(float4*)&Bs[bk * BN + ((bn + 4) ^ ((bk & 3) << 3))] = pb1;
        __syncthreads();

        // prefetch next tile
        if (k0 + BK < F) {
            int kn = k0 + BK;
            int grow = row0 + am;
            if (grow < NN) {
                pa0 = *(const float4*)&A[grow * F + kn + ak];
                pa1 = *(const float4*)&A[grow * F + kn + ak + 4];
            } else {
                pa0 = make_float4(0.f, 0.f, 0.f, 0.f);
                pa1 = pa0;
            }
            pb0 = *(const float4*)&B[(kn + bk) * F + col0 + bn];
            pb1 = *(const float4*)&B[(kn + bk) * F + col0 + bn + 4];
        }

        // compute: two k8 steps
#pragma unroll
        for (int k8 = 0; k8 < 2; k8++) {
            int kb = k8 * 8;
            uint32_t aH[2][4], aL[2][4];
#pragma unroll
            for (int mt = 0; mt < 2; mt++) {
                int m0 = wm * 32 + mt * 16;
                int xr  = (m0 + r) ^ (c << 3);
                int xr8 = (m0 + r + 8) ^ (c << 3);
                float f0 = As[(kb + c) * BM + xr];
                float f1 = As[(kb + c) * BM + xr8];
                float f2 = As[(kb + c + 4) * BM + xr];
                float f3 = As[(kb + c + 4) * BM + xr8];
                tf32_split(f0, aH[mt][0], aL[mt][0]);
                tf32_split(f1, aH[mt][1], aL[mt][1]);
                tf32_split(f2, aH[mt][2], aL[mt][2]);
                tf32_split(f3, aH[mt][3], aL[mt][3]);
            }
#pragma unroll
            for (int nt = 0; nt < 8; nt++) {
                int n_ = wn * 64 + nt * 8 + r;
                int xn = n_ ^ (c << 3);
                float g0 = Bs[(kb + c) * BN + xn];
                float g1 = Bs[(kb + c + 4) * BN + xn];
                uint32_t bH[2], bL[2];
                tf32_split(g0, bH[0], bL[0]);
                tf32_split(g1, bH[1], bL[1]);
#pragma unroll
                for (int mt = 0; mt < 2; mt++) {
                    mma_tf32(acc[mt][nt], aH[mt], bH);
                    mma_tf32(acc[mt][nt], aH[mt], bL);
                    mma_tf32(acc[mt][nt], aL[mt], bH);
                }
            }
        }
        __syncthreads();
    }

    // epilogue -> g_h (fp32) + g_h16 (fp16 gather copy)
#pragma unroll
    for (int mt = 0; mt < 2; mt++) {
        int rb = row0 + wm * 32 + mt * 16 + r;
#pragma unroll
        for (int nt = 0; nt < 8; nt++) {
            int cb = col0 + wn * 64 + nt * 8 + 2 * c;
            if (rb < NN) {
                *(float2*)&g_h[rb * F + cb] = make_float2(acc[mt][nt][0], acc[mt][nt][1]);
                *(__half2*)&g_h16[rb * F + cb] = __floats2half2_rn(acc[mt][nt][0], acc[mt][nt][1]);
            }
            if (rb + 8 < NN) {
                *(float2*)&g_h[(rb + 8) * F + cb] = make_float2(acc[mt][nt][2], acc[mt][nt][3]);
                *(__half2*)&g_h16[(rb + 8) * F + cb] = __floats2half2_rn(acc[mt][nt][2], acc[mt][nt][3]);
            }
        }
    }
}

// ---------------- attention coefficients: a_src, a_dst per (node, head) ----------------
__global__ void attn_kernel(const float* __restrict__ att_src,
                            const float* __restrict__ att_dst) {
    int idx = blockIdx.x * blockDim.x + threadIdx.x;
    if (idx >= NN * HEADS) return;
    int n = idx >> 2;
    int h = idx & 3;
    const float4* hp = (const float4*)&g_h[n * F + h * CH];
    const float4* as = (const float4*)&att_src[h * CH];
    const float4* ad = (const float4*)&att_dst[h * CH];
    float ssum = 0.f, dsum = 0.f;
#pragma unroll
    for (int i = 0; i < 16; i++) {
        float4 v = hp[i];
        float4 s4 = as[i];
        float4 d4 = ad[i];
        ssum += v.x * s4.x + v.y * s4.y + v.z * s4.z + v.w * s4.w;
        dsum += v.x * d4.x + v.y * d4.y + v.z * d4.z + v.w * d4.w;
    }
    g_asrc[idx] = ssum;
    g_adst[idx] = dsum;
}

// ---------------- CSR build ----------------
__global__ void hist_kernel(const int* __restrict__ dst) {
    int e = blockIdx.x * blockDim.x + threadIdx.x;
    if (e < NE) atomicAdd(&g_cnt[dst[e]], 1);
}

// single-block exclusive scan over g_cnt -> g_start, g_cursor (int4 per thread)
__global__ void scan_kernel() {
    __shared__ int warp_sums[32];
    __shared__ int s_carry;
    int tid = threadIdx.x;
    int lane = tid & 31;
    int wid = tid >> 5;
    if (tid == 0) s_carry = 0;
    __syncthreads();
    for (int base = 0; base < NN; base += 4096) {
        int i = base + tid * 4;
        int4 v = make_int4(0, 0, 0, 0);
        if (i < NN) v = *(const int4*)&g_cnt[i];     // NN % 4 == 0
        int t = v.x + v.y + v.z + v.w;
        int x = t;
#pragma unroll
        for (int o = 1; o < 32; o <<= 1) {
            int y = __shfl_up_sync(0xffffffffu, x, o);
            if (lane >= o) x += y;
        }
        if (lane == 31) warp_sums[wid] = x;
        __syncthreads();
        if (wid == 0) {
            int ws = warp_sums[lane];
#pragma unroll
            for (int o = 1; o < 32; o <<= 1) {
                int y = __shfl_up_sync(0xffffffffu, ws, o);
                if (lane >= o) ws += y;
            }
            warp_sums[lane] = ws;
        }
        __syncthreads();
        int excl = x - t + (wid > 0 ? warp_sums[wid - 1] : 0) + s_carry;
        if (i < NN) {
            int4 e4 = make_int4(excl, excl + v.x, excl + v.x + v.y, excl + v.x + v.y + v.z);
            *(int4*)&g_start[i]  = e4;
            *(int4*)&g_cursor[i] = e4;
        }
        __syncthreads();
        if (tid == 0) s_carry += warp_sums[31];
        __syncthreads();
    }
    if (tid == 0) g_start[NN] = s_carry;
}

__global__ void scatter_kernel(const int* __restrict__ src,
                               const int* __restrict__ dst) {
    int e = blockIdx.x * blockDim.x + threadIdx.x;
    if (e >= NE) return;
    int d = dst[e];
    int p = atomicAdd(&g_cursor[d], 1);
    g_csr_src[p] = src[e];
}

// ---------------- fused aggregation: warp per dst node, register accumulators ------
// out[d] = elu( (wself*h[d] + sum_e w_e*h16[src_e]) / (wself + sum w_e + 1e-16) + bias )
__global__ void __launch_bounds__(256)
agg_kernel(const float* __restrict__ bias, float* __restrict__ outp, int toFeat) {
    int d = blockIdx.x * 8 + (threadIdx.x >> 5);
    if (d >= NN) return;
    int lane = threadIdx.x & 31;
    int h = lane >> 3;                      // head for this lane's 8 columns

    float adst_h = g_adst[d * 4 + h];
    float wself  = expf(lrelu(g_asrc[d * 4 + h] + adst_h));

    const float4* hp = (const float4*)&g_h[d * F + lane * 8];
    float4 a0 = hp[0], a1 = hp[1];
    float4 acc0 = make_float4(wself * a0.x, wself * a0.y, wself * a0.z, wself * a0.w);
    float4 acc1 = make_float4(wself * a1.x, wself * a1.y, wself * a1.z, wself * a1.w);
    float denom = wself;

    int s0 = g_start[d];
    int s1 = g_start[d + 1];

    for (int base = s0; base < s1; base += 32) {
        int cnt = min(32, s1 - base);
        int sidx = (lane < cnt) ? g_csr_src[base + lane] : 0;
        int nsub = (cnt + 7) >> 3;
        for (int sub = 0; sub < nsub; sub++) {
            // 32 lanes compute weights for 8 edges x 4 heads in parallel
            int sw = __shfl_sync(0xffffffffu, sidx, sub * 8 + (lane & 7));
            float wl = expf(lrelu(g_asrc[sw * 4 + h] + adst_h));
            int jend = min(8, cnt - sub * 8);
#pragma unroll 4
            for (int j = 0; j < jend; j++) {
                int s  = __shfl_sync(0xffffffffu, sidx, sub * 8 + j);
                float w = __shfl_sync(0xffffffffu, wl, (lane & 24) + j);
                uint4 raw = *(const uint4*)&g_h16[s * F + lane * 8];
                float2 f0 = __half22float2(*(__half2*)&raw.x);
                float2 f1 = __half22float2(*(__half2*)&raw.y);
                float2 f2 = __half22float2(*(__half2*)&raw.z);
                float2 f3 = __half22float2(*(__half2*)&raw.w);
                acc0.x += w * f0.x; acc0.y += w * f0.y;
                acc0.z += w * f1.x; acc0.w += w * f1.y;
                acc1.x += w * f2.x; acc1.y += w * f2.y;
                acc1.z += w * f3.x; acc1.w += w * f3.y;
                denom += w;
            }
        }
    }

    float inv = 1.f / (denom + 1e-16f);
    float4 b0 = *(const float4*)&bias[lane * 8];
    float4 b1 = *(const float4*)&bias[lane * 8 + 4];
    acc0.x = elu1(acc0.x * inv + b0.x);
    acc0.y = elu1(acc0.y * inv + b0.y);
    acc0.z = elu1(acc0.z * inv + b0.z);
    acc0.w = elu1(acc0.w * inv + b0.w);
    acc1.x = elu1(acc1.x * inv + b1.x);
    acc1.y = elu1(acc1.y * inv + b1.y);
    acc1.z = elu1(acc1.z * inv + b1.z);
    acc1.w = elu1(acc1.w * inv + b1.w);

    float* dp = (toFeat ? g_feat : outp) + d * F + lane * 8;
    *(float4*)dp       = acc0;
    *(float4*)(dp + 4) = acc1;
}

// ---------------- launch ----------------
static void run_layer(const float* x_or_null, int useFeat,
                      const float* W, const float* att_src, const float* att_dst,
                      const float* bias, float* outp, int toFeat) {
    dim3 gemmGrid(F / BN, (NN + BM - 1) / BM);
    gemm_tf32_kernel<<<gemmGrid, 256>>>(x_or_null, W, useFeat);

    int nh = NN * HEADS;
    attn_kernel<<<(nh + 255) / 256, 256>>>(att_src, att_dst);
    agg_kernel<<<(NN + 7) / 8, 256>>>(bias, outp, toFeat);
}

extern "C" void kernel_launch(void* const* d_in, const int* in_sizes, int n_in,
                              void* d_out, int out_size) {
    const float* x        = (const float*)d_in[0];
    const int*   ei       = (const int*)  d_in[1];
    const float* W1       = (const float*)d_in[2];
    const float* att_src1 = (const float*)d_in[3];
    const float* att_dst1 = (const float*)d_in[4];
    const float* b1       = (const float*)d_in[5];
    const float* W2       = (const float*)d_in[6];
    const float* att_src2 = (const float*)d_in[7];
    const float* att_dst2 = (const float*)d_in[8];
    const float* b2       = (const float*)d_in[9];
    float* out = (float*)d_out;

    const int* src = ei;            // edge_index[0]
    const int* dst = ei + NE;       // edge_index[1]

    // CSR build (shared by both layers)
    void* cnt_ptr = nullptr;
    cudaGetSymbolAddress(&cnt_ptr, g_cnt);
    cudaMemsetAsync(cnt_ptr, 0, NN * sizeof(int));
    hist_kernel<<<(NE + 255) / 256, 256>>>(dst);
    scan_kernel<<<1, 1024>>>();
    scatter_kernel<<<(NE + 255) / 256, 256>>>(src, dst);

    // layer 1: x -> g_feat
    run_layer(x, 0, W1, att_src1, att_dst1, b1, nullptr, 1);
    // layer 2: g_feat -> out
    run_layer(nullptr, 1, W2, att_src2, att_dst2, b2, out, 0);
}

// round 14
// speedup vs baseline: 1.6079x; 1.1307x over previous
#include <cuda_runtime.h>
#include <cuda_bf16.h>
#include <cuda_fp16.h>
#include <cstdint>

// Problem constants
#define NN 50000      // nodes
#define NE 800000     // edges
#define HEADS 4
#define CH 64
#define F 256         // HEADS*CH == input dim for both layers

// GEMM tiling
#define BM 128
#define BN 128
#define BK 16
#define NT (F / BK)   // 16 k-tiles

// ---------------- scratch (device globals; no allocation allowed) ----------------
__device__ float  g_h[NN * F];      // post-GEMM features (fp32)
__device__ __half g_h16[NN * F];    // fp16 copy for the gather path
__device__ float  g_feat[NN * F];   // layer-1 output / layer-2 input
__device__ float  g_asrc[NN * HEADS];
__device__ float  g_adst[NN * HEADS];
__device__ int    g_cnt[NN];        // in-degree histogram
__device__ int    g_start[NN + 1];  // CSR row starts (by dst)
__device__ int    g_cursor[NN];     // scatter cursors
__device__ int    g_csr_src[NE];    // src node id per CSR slot

// ---------------- helpers ----------------
__device__ __forceinline__ float lrelu(float x) { return x > 0.f ? x : 0.2f * x; }
__device__ __forceinline__ float elu1(float x)  { return x > 0.f ? x : expf(x) - 1.f; }

// tf32 mma: D += A(16x8, row) * B(8x8, col), fp32 accum
__device__ __forceinline__ void mma_tf32(float* d, const uint32_t* a, const uint32_t* b) {
    asm volatile(
        "mma.sync.aligned.m16n8k8.row.col.f32.tf32.tf32.f32 "
        "{%0,%1,%2,%3}, {%4,%5,%6,%7}, {%8,%9}, {%0,%1,%2,%3};"
        : "+f"(d[0]), "+f"(d[1]), "+f"(d[2]), "+f"(d[3])
        : "r"(a[0]), "r"(a[1]), "r"(a[2]), "r"(a[3]), "r"(b[0]), "r"(b[1]));
}

// split fp32 into tf32 hi + tf32 lo (truncation; lo*lo term ~2^-22, dropped)
__device__ __forceinline__ void tf32_split(float f, uint32_t& hi, uint32_t& lo) {
    hi = __float_as_uint(f) & 0xFFFFE000u;
    float lf = f - __uint_as_float(hi);
    lo = __float_as_uint(lf) & 0xFFFFE000u;
}

// ---------------- GEMM + fused attn: g_h = A @ B, g_asrc/g_adst from acc regs ------
// 128x128 block tile, BK=16, 256 threads (8 warps, 4x2), warp tile 32x64.
// Double-buffered SMEM (1 barrier/iter). Each warp tile = exactly 1 head x 32 rows,
// so attention coefficients are computed warp-locally (no atomics).
__global__ void __launch_bounds__(256, 2)
gemm_tf32_kernel(const float* __restrict__ A, const float* __restrict__ B,
                 const float* __restrict__ att_src, const float* __restrict__ att_dst) {
    __shared__ float As[2][BK * BM];
    __shared__ float Bs[2][BK * BN];

    int tid  = threadIdx.x;
    int warp = tid >> 5;
    int lane = tid & 31;
    int wm = warp >> 1;              // 0..3
    int wn = warp & 1;               // 0..1
    int row0 = blockIdx.y * BM;
    int col0 = blockIdx.x * BN;
    int c = lane & 3;                // quad column
    int r = lane >> 2;               // quad row (0..7)

    float acc[2][8][4];
#pragma unroll
    for (int mt = 0; mt < 2; mt++)
#pragma unroll
        for (int nt = 0; nt < 8; nt++)
#pragma unroll
            for (int i = 0; i < 4; i++) acc[mt][nt][i] = 0.f;

    // ---- gmem load mapping ----
    int am = tid >> 1;               // A row within tile (0..127)
    int ak = (tid & 1) * 8;          // A k offset (0 or 8)
    int bk = tid >> 4;               // B k row (0..15)
    int bn = (tid & 15) * 8;         // B n offset (0..120, step 8)

    float4 pa0, pa1, pb0, pb1;
    {
        int grow = row0 + am;
        if (grow < NN) {
            pa0 = *(const float4*)&A[grow * F + ak];
            pa1 = *(const float4*)&A[grow * F + ak + 4];
        } else {
            pa0 = make_float4(0.f, 0.f, 0.f, 0.f);
            pa1 = pa0;
        }
        pb0 = *(const float4*)&B[bk * F + col0 + bn];
        pb1 = *(const float4*)&B[bk * F + col0 + bn + 4];
    }

    // store tile 0 into buffer 0
    {
        float av[8] = {pa0.x, pa0.y, pa0.z, pa0.w, pa1.x, pa1.y, pa1.z, pa1.w};
#pragma unroll
        for (int j = 0; j < 8; j++) {
            int kk = ak + j;
            As[0][kk * BM + (am ^ ((kk & 3) << 3))] = av[j];
        }
        *(float4*)&Bs[0][bk * BN + (bn ^ ((bk & 3) << 3))]       = pb0;
        *(float4*)&Bs[0][bk * BN + ((bn + 4) ^ ((bk & 3) << 3))] = pb1;
    }
    __syncthreads();

    for (int it = 0; it < NT; it++) {
        int cur = it & 1;

        // prefetch next tile into regs (loads in flight during compute)
        if (it + 1 < NT) {
            int kn = (it + 1) * BK;
            int grow = row0 + am;
            if (grow < NN) {
                pa0 = *(const float4*)&A[grow * F + kn + ak];
                pa1 = *(const float4*)&A[grow * F + kn + ak + 4];
            } else {
                pa0 = make_float4(0.f, 0.f, 0.f, 0.f);
                pa1 = pa0;
            }
            pb0 = *(const float4*)&B[(kn + bk) * F + col0 + bn];
            pb1 = *(const float4*)&B[(kn + bk) * F + col0 + bn + 4];
        }

        // compute from buf[cur]: two k8 steps
#pragma unroll
        for (int k8 = 0; k8 < 2; k8++) {
            int kb = k8 * 8;
            uint32_t aH[2][4], aL[2][4];
#pragma unroll
            for (int mt = 0; mt < 2; mt++) {
                int m0 = wm * 32 + mt * 16;
                int xr  = (m0 + r) ^ (c << 3);
                int xr8 = (m0 + r + 8) ^ (c << 3);
                float f0 = As[cur][(kb + c) * BM + xr];
                float f1 = As[cur][(kb + c) * BM + xr8];
                float f2 = As[cur][(kb + c + 4) * BM + xr];
                float f3 = As[cur][(kb + c + 4) * BM + xr8];
                tf32_split(f0, aH[mt][0], aL[mt][0]);
                tf32_split(f1, aH[mt][1], aL[mt][1]);
                tf32_split(f2, aH[mt][2], aL[mt][2]);
                tf32_split(f3, aH[mt][3], aL[mt][3]);
            }
#pragma unroll
            for (int nt = 0; nt < 8; nt++) {
                int n_ = wn * 64 + nt * 8 + r;
                int xn = n_ ^ (c << 3);
                float g0 = Bs[cur][(kb + c) * BN + xn];
                float g1 = Bs[cur][(kb + c + 4) * BN + xn];
                uint32_t bH[2], bL[2];
                tf32_split(g0, bH[0], bL[0]);
                tf32_split(g1, bH[1], bL[1]);
#pragma unroll
                for (int mt = 0; mt < 2; mt++) {
                    mma_tf32(acc[mt][nt], aH[mt], bH);
                    mma_tf32(acc[mt][nt], aH[mt], bL);
                    mma_tf32(acc[mt][nt], aL[mt], bH);
                }
            }
        }

        // store next tile into the other buffer; single barrier per iteration
        if (it + 1 < NT) {
            int nxt = cur ^ 1;
            float av[8] = {pa0.x, pa0.y, pa0.z, pa0.w, pa1.x, pa1.y, pa1.z, pa1.w};
#pragma unroll
            for (int j = 0; j < 8; j++) {
                int kk = ak + j;
                As[nxt][kk * BM + (am ^ ((kk & 3) << 3))] = av[j];
            }
            *(float4*)&Bs[nxt][bk * BN + (bn ^ ((bk & 3) << 3))]       = pb0;
            *(float4*)&Bs[nxt][bk * BN + ((bn + 4) ^ ((bk & 3) << 3))] = pb1;
            __syncthreads();
        }
    }

    // ---- epilogue: write g_h / g_h16, and fused attention coefficients ----
    int head = (col0 >> 6) + wn;           // this warp's head (warp tile = 1 head)
    const float* as_v = &att_src[head * CH];
    const float* ad_v = &att_dst[head * CH];

#pragma unroll
    for (int mt = 0; mt < 2; mt++) {
        int rb = row0 + wm * 32 + mt * 16 + r;
        float ssA = 0.f, sdA = 0.f;        // row rb
        float ssB = 0.f, sdB = 0.f;        // row rb+8
#pragma unroll
        for (int nt = 0; nt < 8; nt++) {
            int cb = col0 + wn * 64 + nt * 8 + 2 * c;
            if (rb < NN) {
                *(float2*)&g_h[rb * F + cb] = make_float2(acc[mt][nt][0], acc[mt][nt][1]);
                *(__half2*)&g_h16[rb * F + cb] = __floats2half2_rn(acc[mt][nt][0], acc[mt][nt][1]);
            }
            if (rb + 8 < NN) {
                *(float2*)&g_h[(rb + 8) * F + cb] = make_float2(acc[mt][nt][2], acc[mt][nt][3]);
                *(__half2*)&g_h16[(rb + 8) * F + cb] = __floats2half2_rn(acc[mt][nt][2], acc[mt][nt][3]);
            }
            int j0 = nt * 8 + 2 * c;       // column within head (0..63)
            float a0v = as_v[j0], a1v = as_v[j0 + 1];
            float d0v = ad_v[j0], d1v = ad_v[j0 + 1];
            ssA += acc[mt][nt][0] * a0v + acc[mt][nt][1] * a1v;
            sdA += acc[mt][nt][0] * d0v + acc[mt][nt][1] * d1v;
            ssB += acc[mt][nt][2] * a0v + acc[mt][nt][3] * a1v;
            sdB += acc[mt][nt][2] * d0v + acc[mt][nt][3] * d1v;
        }
        // reduce over the 4 c-lanes (lane bits 0..1)
#pragma unroll
        for (int o = 1; o <= 2; o <<= 1) {
            ssA += __shfl_xor_sync(0xffffffffu, ssA, o);
            sdA += __shfl_xor_sync(0xffffffffu, sdA, o);
            ssB += __shfl_xor_sync(0xffffffffu, ssB, o);
            sdB += __shfl_xor_sync(0xffffffffu, sdB, o);
        }
        if (c == 0) {
            if (rb < NN)     { g_asrc[rb * 4 + head] = ssA; g_adst[rb * 4 + head] = sdA; }
            if (rb + 8 < NN) { g_asrc[(rb + 8) * 4 + head] = ssB; g_adst[(rb + 8) * 4 + head] = sdB; }
        }
    }
}

// ---------------- CSR build ----------------
__global__ void hist_kernel(const int* __restrict__ dst) {
    int e = blockIdx.x * blockDim.x + threadIdx.x;
    if (e < NE) atomicAdd(&g_cnt[dst[e]], 1);
}

// single-block exclusive scan over g_cnt -> g_start, g_cursor (int4 per thread)
__global__ void scan_kernel() {
    __shared__ int warp_sums[32];
    __shared__ int s_carry;
    int tid = threadIdx.x;
    int lane = tid & 31;
    int wid = tid >> 5;
    if (tid == 0) s_carry = 0;
    __syncthreads();
    for (int base = 0; base < NN; base += 4096) {
        int i = base + tid * 4;
        int4 v = make_int4(0, 0, 0, 0);
        if (i < NN) v = *(const int4*)&g_cnt[i];     // NN % 4 == 0
        int t = v.x + v.y + v.z + v.w;
        int x = t;
#pragma unroll
        for (int o = 1; o < 32; o <<= 1) {
            int y = __shfl_up_sync(0xffffffffu, x, o);
            if (lane >= o) x += y;
        }
        if (lane == 31) warp_sums[wid] = x;
        __syncthreads();
        if (wid == 0) {
            int ws = warp_sums[lane];
#pragma unroll
            for (int o = 1; o < 32; o <<= 1) {
                int y = __shfl_up_sync(0xffffffffu, ws, o);
                if (lane >= o) ws += y;
            }
            warp_sums[lane] = ws;
        }
        __syncthreads();
        int excl = x - t + (wid > 0 ? warp_sums[wid - 1] : 0) + s_carry;
        if (i < NN) {
            int4 e4 = make_int4(excl, excl + v.x, excl + v.x + v.y, excl + v.x + v.y + v.z);
            *(int4*)&g_start[i]  = e4;
            *(int4*)&g_cursor[i] = e4;
        }
        __syncthreads();
        if (tid == 0) s_carry += warp_sums[31];
        __syncthreads();
    }
    if (tid == 0) g_start[NN] = s_carry;
}

__global__ void scatter_kernel(const int* __restrict__ src,
                               const int* __restrict__ dst) {
    int e = blockIdx.x * blockDim.x + threadIdx.x;
    if (e >= NE) return;
    int d = dst[e];
    int p = atomicAdd(&g_cursor[d], 1);
    g_csr_src[p] = src[e];
}

// ---------------- fused aggregation: warp per dst node, register accumulators ------
// out[d] = elu( (wself*h[d] + sum_e w_e*h16[src_e]) / (wself + sum w_e + 1e-16) + bias )
__global__ void __launch_bounds__(256)
agg_kernel(const float* __restrict__ bias, float* __restrict__ outp, int toFeat) {
    int d = blockIdx.x * 8 + (threadIdx.x >> 5);
    if (d >= NN) return;
    int lane = threadIdx.x & 31;
    int h = lane >> 3;                      // head for this lane's 8 columns

    float adst_h = g_adst[d * 4 + h];
    float wself  = expf(lrelu(g_asrc[d * 4 + h] + adst_h));

    const float4* hp = (const float4*)&g_h[d * F + lane * 8];
    float4 a0 = hp[0], a1 = hp[1];
    float4 acc0 = make_float4(wself * a0.x, wself * a0.y, wself * a0.z, wself * a0.w);
    float4 acc1 = make_float4(wself * a1.x, wself * a1.y, wself * a1.z, wself * a1.w);
    float denom = wself;

    int s0 = g_start[d];
    int s1 = g_start[d + 1];

    for (int base = s0; base < s1; base += 32) {
        int cnt = min(32, s1 - base);
        int sidx = (lane < cnt) ? g_csr_src[base + lane] : 0;
        int nsub = (cnt + 7) >> 3;
        for (int sub = 0; sub < nsub; sub++) {
            // 32 lanes compute weights for 8 edges x 4 heads in parallel
            int sw = __shfl_sync(0xffffffffu, sidx, sub * 8 + (lane & 7));
            float wl = expf(lrelu(g_asrc[sw * 4 + h] + adst_h));
            int jend = min(8, cnt - sub * 8);
#pragma unroll 4
            for (int j = 0; j < jend; j++) {
                int s  = __shfl_sync(0xffffffffu, sidx, sub * 8 + j);
                float w = __shfl_sync(0xffffffffu, wl, (lane & 24) + j);
                uint4 raw = *(const uint4*)&g_h16[s * F + lane * 8];
                float2 f0 = __half22float2(*(__half2*)&raw.x);
                float2 f1 = __half22float2(*(__half2*)&raw.y);
                float2 f2 = __half22float2(*(__half2*)&raw.z);
                float2 f3 = __half22float2(*(__half2*)&raw.w);
                acc0.x += w * f0.x; acc0.y += w * f0.y;
                acc0.z += w * f1.x; acc0.w += w * f1.y;
                acc1.x += w * f2.x; acc1.y += w * f2.y;
                acc1.z += w * f3.x; acc1.w += w * f3.y;
                denom += w;
            }
        }
    }

    float inv = 1.f / (denom + 1e-16f);
    float4 b0 = *(const float4*)&bias[lane * 8];
    float4 b1 = *(const float4*)&bias[lane * 8 + 4];
    acc0.x = elu1(acc0.x * inv + b0.x);
    acc0.y = elu1(acc0.y * inv + b0.y);
    acc0.z = elu1(acc0.z * inv + b0.z);
    acc0.w = elu1(acc0.w * inv + b0.w);
    acc1.x = elu1(acc1.x * inv + b1.x);
    acc1.y = elu1(acc1.y * inv + b1.y);
    acc1.z = elu1(acc1.z * inv + b1.z);
    acc1.w = elu1(acc1.w * inv + b1.w);

    float* dp = (toFeat ? g_feat : outp) + d * F + lane * 8;
    *(float4*)dp       = acc0;
    *(float4*)(dp + 4) = acc1;
}

// ---------------- launch ----------------
static void run_layer(const float* Ain,
                      const float* W, const float* att_src, const float* att_dst,
                      const float* bias, float* outp, int toFeat) {
    dim3 gemmGrid(F / BN, (NN + BM - 1) / BM);
    gemm_tf32_kernel<<<gemmGrid, 256>>>(Ain, W, att_src, att_dst);
    agg_kernel<<<(NN + 7) / 8, 256>>>(bias, outp, toFeat);
}

extern "C" void kernel_launch(void* const* d_in, const int* in_sizes, int n_in,
                              void* d_out, int out_size) {
    const float* x        = (const float*)d_in[0];
    const int*   ei       = (const int*)  d_in[1];
    const float* W1       = (const float*)d_in[2];
    const float* att_src1 = (const float*)d_in[3];
    const float* att_dst1 = (const float*)d_in[4];
    const float* b1       = (const float*)d_in[5];
    const float* W2       = (const float*)d_in[6];
    const float* att_src2 = (const float*)d_in[7];
    const float* att_dst2 = (const float*)d_in[8];
    const float* b2       = (const float*)d_in[9];
    float* out = (float*)d_out;

    const int* src = ei;            // edge_index[0]
    const int* dst = ei + NE;       // edge_index[1]

    // CSR build (shared by both layers)
    void* cnt_ptr = nullptr;
    cudaGetSymbolAddress(&cnt_ptr, g_cnt);
    cudaMemsetAsync(cnt_ptr, 0, NN * sizeof(int));
    hist_kernel<<<(NE + 255) / 256, 256>>>(dst);
    scan_kernel<<<1, 1024>>>();
    scatter_kernel<<<(NE + 255) / 256, 256>>>(src, dst);

    // layer 2 input pointer (device global address, host-visible)
    void* feat_ptr = nullptr;
    cudaGetSymbolAddress(&feat_ptr, g_feat);

    // layer 1: x -> g_feat
    run_layer(x, W1, att_src1, att_dst1, b1, nullptr, 1);
    // layer 2: g_feat -> out
    run_layer((const float*)feat_ptr, W2, att_src2, att_dst2, b2, out, 0);
}